// round 3
// baseline (speedup 1.0000x reference)
#include <cuda_runtime.h>
#include <math.h>

#define NMAX 100000
#define EMAX 1600000
#define HEADS 8
#define NBUCK 4096

typedef unsigned long long ull;

// ---------------- scratch (static device globals; no runtime alloc) ----------------
__device__ float g_xh1[(size_t)NMAX * 256];
__device__ float g_xh2[(size_t)NMAX * 128];
__device__ float g_agg1[(size_t)NMAX * 32];
__device__ float g_agg2[(size_t)NMAX * 16];
__device__ float g_asrc[(size_t)NMAX * HEADS];
__device__ float g_adst[(size_t)NMAX * HEADS];
__device__ float g_den[(size_t)2 * NMAX * HEADS];
__device__ float g_h1[(size_t)NMAX * 32];
__device__ int   g_cnt[NBUCK];
__device__ int   g_cursor[NBUCK];
__device__ int2  g_esort[(size_t)(EMAX + NMAX)];

// ---------------- helpers ----------------
__device__ __forceinline__ void red_add_v4(float* p, float4 v) {
    asm volatile("red.global.add.v4.f32 [%0], {%1,%2,%3,%4};"
                 :: "l"(p), "f"(v.x), "f"(v.y), "f"(v.z), "f"(v.w)
                 : "memory");
}
__device__ __forceinline__ float lrelu_exp(float v) {
    v = v > 0.0f ? v : 0.2f * v;
    return expf(v);
}
__device__ __forceinline__ ull pack2(float v) {
    ull r; asm("mov.b64 %0, {%1, %1};" : "=l"(r) : "f"(v)); return r;
}
__device__ __forceinline__ void fma2(ull& d, ull a, ull b) {
    asm("fma.rn.f32x2 %0, %1, %2, %0;" : "+l"(d) : "l"(a), "l"(b));
}
__device__ __forceinline__ float2 unpack2(ull v) {
    float2 f; asm("mov.b64 {%0, %1}, %2;" : "=f"(f.x), "=f"(f.y) : "l"(v)); return f;
}

// ---------------- edge bucket sort by src (32 nodes per bucket) ----------------
__global__ void hist_kernel(const int* __restrict__ ei, int E, int N, int* __restrict__ cnt) {
    __shared__ int h[NBUCK];
    for (int i = threadIdx.x; i < NBUCK; i += blockDim.x) h[i] = 0;
    __syncthreads();
    int EN = E + N;
    for (int k = blockIdx.x * blockDim.x + threadIdx.x; k < EN; k += gridDim.x * blockDim.x) {
        int src = (k < E) ? __ldg(ei + k) : (k - E);
        atomicAdd(&h[src >> 5], 1);
    }
    __syncthreads();
    for (int i = threadIdx.x; i < NBUCK; i += blockDim.x)
        if (h[i]) atomicAdd(&cnt[i], h[i]);
}

__global__ void scan_kernel(const int* __restrict__ cnt, int* __restrict__ off) {
    __shared__ int s[1024];
    int tid = threadIdx.x;
    int base = tid * 4;
    int a0 = cnt[base], a1 = cnt[base + 1], a2 = cnt[base + 2], a3 = cnt[base + 3];
    int t = a0 + a1 + a2 + a3;
    s[tid] = t;
    __syncthreads();
    for (int d = 1; d < 1024; d <<= 1) {
        int v = (tid >= d) ? s[tid - d] : 0;
        __syncthreads();
        s[tid] += v;
        __syncthreads();
    }
    int ex = s[tid] - t;
    off[base]     = ex;
    off[base + 1] = ex + a0;
    off[base + 2] = ex + a0 + a1;
    off[base + 3] = ex + a0 + a1 + a2;
}

__global__ void scatter_kernel(const int* __restrict__ ei, int E, int N,
                               int* __restrict__ cursor, int2* __restrict__ es) {
    int EN = E + N;
    for (int k = blockIdx.x * blockDim.x + threadIdx.x; k < EN; k += gridDim.x * blockDim.x) {
        int src, dst;
        if (k < E) { src = __ldg(ei + k); dst = __ldg(ei + E + k); }
        else       { src = dst = k - E; }
        int pos = atomicAdd(&cursor[src >> 5], 1);
        es[pos] = make_int2(src, dst);
    }
}

// ---------------- fused GEMM (fp32x2 packed FMA) + attention logits ----------------
template<int F, int CO, int HS>
__global__ void gemm_att_kernel(const float* __restrict__ X, const float* __restrict__ W,
                                const float* __restrict__ a_src_w, const float* __restrict__ a_dst_w,
                                float* __restrict__ XH, float* __restrict__ ASRC,
                                float* __restrict__ ADST, int N) {
    constexpr int QUADS = CO / 4;
    constexpr int RG    = 512 / QUADS;
    constexpr int ROWS  = RG * 8;
    constexpr int GROUP = HS / 4;

    extern __shared__ float sh[];
    float* Ws = sh;                       // F*CO
    float* Xs = sh + F * CO;              // ROWS*F
    float4* Ws4 = reinterpret_cast<float4*>(Ws);
    const ulonglong2* Wsu = reinterpret_cast<const ulonglong2*>(Ws);
    float4* Xs4 = reinterpret_cast<float4*>(Xs);

    const int tid = threadIdx.x;
    const int cg  = tid % QUADS;
    const int rg  = tid / QUADS;

    const float4* Wg4 = reinterpret_cast<const float4*>(W);
    for (int i = tid; i < F * CO / 4; i += 512) Ws4[i] = Wg4[i];

    const float4 av_s = reinterpret_cast<const float4*>(a_src_w)[cg];
    const float4 av_d = reinterpret_cast<const float4*>(a_dst_w)[cg];

    for (int n0 = blockIdx.x * ROWS; n0 < N; n0 += gridDim.x * ROWS) {
        __syncthreads();
        for (int i = tid; i < ROWS * F / 4; i += 512) {
            int row  = i / (F / 4);
            int col4 = i % (F / 4);
            int n = n0 + row;
            Xs4[i] = (n < N) ? reinterpret_cast<const float4*>(X)[(size_t)n * (F / 4) + col4]
                             : make_float4(0.f, 0.f, 0.f, 0.f);
        }
        __syncthreads();

        // accumulators: 8 rows x 2 column-pairs, packed f32x2
        ull acc[8][2];
        #pragma unroll
        for (int r = 0; r < 8; r++) { acc[r][0] = 0ULL; acc[r][1] = 0ULL; }

        #pragma unroll 4
        for (int f = 0; f < F; f++) {
            ulonglong2 w = Wsu[f * QUADS + cg];   // w.x={c0,c1}, w.y={c2,c3}
            #pragma unroll
            for (int r = 0; r < 8; r++) {
                ull xv2 = pack2(Xs[(rg * 8 + r) * F + f]);
                fma2(acc[r][0], xv2, w.x);
                fma2(acc[r][1], xv2, w.y);
            }
        }

        #pragma unroll
        for (int r = 0; r < 8; r++) {
            int n = n0 + rg * 8 + r;
            if (n >= N) continue;
            float2 lo = unpack2(acc[r][0]);
            float2 hi = unpack2(acc[r][1]);
            float4 o = make_float4(lo.x, lo.y, hi.x, hi.y);
            reinterpret_cast<float4*>(XH)[(size_t)n * QUADS + cg] = o;
            float ps = o.x * av_s.x + o.y * av_s.y + o.z * av_s.z + o.w * av_s.w;
            float pd = o.x * av_d.x + o.y * av_d.y + o.z * av_d.z + o.w * av_d.w;
            #pragma unroll
            for (int s = GROUP / 2; s > 0; s >>= 1) {
                ps += __shfl_xor_sync(0xffffffffu, ps, s);
                pd += __shfl_xor_sync(0xffffffffu, pd, s);
            }
            if ((cg % GROUP) == 0) {
                int h = cg / GROUP;
                ASRC[(size_t)n * HEADS + h] = ps;
                ADST[(size_t)n * HEADS + h] = pd;
            }
        }
    }
}

// ---------------- denominator pass (sorted edges) ----------------
__global__ void den_kernel(const int2* __restrict__ es, int EN,
                           const float* __restrict__ ASRC, const float* __restrict__ ADST,
                           float* __restrict__ DEN) {
    int k = blockIdx.x * blockDim.x + threadIdx.x;
    if (k >= EN) return;
    int2 e = __ldg(es + k);

    float4 a0 = __ldg(reinterpret_cast<const float4*>(ASRC) + (size_t)e.x * 2 + 0);
    float4 a1 = __ldg(reinterpret_cast<const float4*>(ASRC) + (size_t)e.x * 2 + 1);
    float4 b0 = __ldg(reinterpret_cast<const float4*>(ADST) + (size_t)e.y * 2 + 0);
    float4 b1 = __ldg(reinterpret_cast<const float4*>(ADST) + (size_t)e.y * 2 + 1);

    float4 e0, e1;
    e0.x = lrelu_exp(a0.x + b0.x); e0.y = lrelu_exp(a0.y + b0.y);
    e0.z = lrelu_exp(a0.z + b0.z); e0.w = lrelu_exp(a0.w + b0.w);
    e1.x = lrelu_exp(a1.x + b1.x); e1.y = lrelu_exp(a1.y + b1.y);
    e1.z = lrelu_exp(a1.z + b1.z); e1.w = lrelu_exp(a1.w + b1.w);

    red_add_v4(DEN + (size_t)e.y * 8 + 0, e0);
    red_add_v4(DEN + (size_t)e.y * 8 + 4, e1);
}

// ---------------- aggregate layer 1 (sorted edges; 8 lanes/edge) ----------------
__global__ void aggregate1_kernel(const int2* __restrict__ es, int EN,
                                  const float* __restrict__ XH,
                                  const float* __restrict__ ASRC, const float* __restrict__ ADST,
                                  const float* __restrict__ DEN, float* __restrict__ AGG) {
    int t = blockIdx.x * blockDim.x + threadIdx.x;
    int k = t >> 3;
    int l = t & 7;
    bool valid = k < EN;
    if (!valid) k = 0;
    int2 e = __ldg(es + k);

    float alpha_l = lrelu_exp(__ldg(ASRC + (size_t)e.x * 8 + l) + __ldg(ADST + (size_t)e.y * 8 + l))
                    / __ldg(DEN + (size_t)e.y * 8 + l);

    const float4* xs = reinterpret_cast<const float4*>(XH) + (size_t)e.x * 64;
    float4 acc = make_float4(0.f, 0.f, 0.f, 0.f);
    #pragma unroll
    for (int h = 0; h < 8; h++) {
        float alpha = __shfl_sync(0xffffffffu, alpha_l, h, 8);
        float4 x = __ldg(xs + h * 8 + l);
        acc.x += alpha * x.x; acc.y += alpha * x.y;
        acc.z += alpha * x.z; acc.w += alpha * x.w;
    }
    if (valid) red_add_v4(AGG + (size_t)e.y * 32 + l * 4, acc);
}

// ---------------- aggregate layer 2 (sorted edges; 4 lanes/edge) ----------------
__global__ void aggregate2_kernel(const int2* __restrict__ es, int EN,
                                  const float* __restrict__ XH,
                                  const float* __restrict__ ASRC, const float* __restrict__ ADST,
                                  const float* __restrict__ DEN, float* __restrict__ AGG) {
    int t = blockIdx.x * blockDim.x + threadIdx.x;
    int k = t >> 2;
    int l = t & 3;
    bool valid = k < EN;
    if (!valid) k = 0;
    int2 e = __ldg(es + k);

    float a0 = lrelu_exp(__ldg(ASRC + (size_t)e.x * 8 + l) + __ldg(ADST + (size_t)e.y * 8 + l))
               / __ldg(DEN + (size_t)e.y * 8 + l);
    float a1 = lrelu_exp(__ldg(ASRC + (size_t)e.x * 8 + l + 4) + __ldg(ADST + (size_t)e.y * 8 + l + 4))
               / __ldg(DEN + (size_t)e.y * 8 + l + 4);

    const float4* xs = reinterpret_cast<const float4*>(XH) + (size_t)e.x * 32;
    float4 acc = make_float4(0.f, 0.f, 0.f, 0.f);
    #pragma unroll
    for (int h = 0; h < 8; h++) {
        float alpha = (h < 4) ? __shfl_sync(0xffffffffu, a0, h, 4)
                              : __shfl_sync(0xffffffffu, a1, h - 4, 4);
        float4 x = __ldg(xs + h * 4 + l);
        acc.x += alpha * x.x; acc.y += alpha * x.y;
        acc.z += alpha * x.z; acc.w += alpha * x.w;
    }
    if (valid) red_add_v4(AGG + (size_t)e.y * 16 + l * 4, acc);
}

// ---------------- finalize layer 1 ----------------
__global__ void finalize1_kernel(const float* __restrict__ agg, const float* __restrict__ b,
                                 float* __restrict__ out, int N) {
    int i = blockIdx.x * blockDim.x + threadIdx.x;
    if (i >= N * 32) return;
    int d = i & 31;
    float m = agg[i] * 0.125f + __ldg(b + d);
    out[i] = m > 0.f ? m : (expf(m) - 1.0f);
}

// ---------------- finalize layer 2 ----------------
__global__ void finalize2_kernel(const float* __restrict__ agg, const float* __restrict__ b,
                                 float* __restrict__ outLsm, float* __restrict__ outLogits,
                                 int N, int writeLogits) {
    int gid = blockIdx.x * blockDim.x + threadIdx.x;
    int n = gid >> 4, c = gid & 15;
    bool valid = n < N;
    float l = 0.f;
    if (valid) l = agg[gid] * 0.125f + __ldg(b + c);
    float m = l;
    #pragma unroll
    for (int s = 8; s > 0; s >>= 1) m = fmaxf(m, __shfl_xor_sync(0xffffffffu, m, s));
    float e = expf(l - m);
    float se = e;
    #pragma unroll
    for (int s = 8; s > 0; s >>= 1) se += __shfl_xor_sync(0xffffffffu, se, s);
    if (valid) {
        outLsm[gid] = l - m - logf(se);
        if (writeLogits) outLogits[gid] = l;
    }
}

// ---------------- host launcher ----------------
extern "C" void kernel_launch(void* const* d_in, const int* in_sizes, int n_in,
                              void* d_out, int out_size) {
    const float* x   = (const float*)d_in[0];
    const int*   ei  = (const int*)d_in[1];
    const float* W1  = (const float*)d_in[2];
    const float* as1 = (const float*)d_in[3];
    const float* ad1 = (const float*)d_in[4];
    const float* b1  = (const float*)d_in[5];
    const float* W2  = (const float*)d_in[6];
    const float* as2 = (const float*)d_in[7];
    const float* ad2 = (const float*)d_in[8];
    const float* b2  = (const float*)d_in[9];

    int N  = in_sizes[0] / 128;
    int E  = in_sizes[1] / 2;
    int EN = E + N;
    float* out = (float*)d_out;

    void *xh1, *xh2, *agg1, *agg2, *asrc, *adst, *den, *h1, *cnt, *cursor, *esort;
    cudaGetSymbolAddress(&xh1,  g_xh1);
    cudaGetSymbolAddress(&xh2,  g_xh2);
    cudaGetSymbolAddress(&agg1, g_agg1);
    cudaGetSymbolAddress(&agg2, g_agg2);
    cudaGetSymbolAddress(&asrc, g_asrc);
    cudaGetSymbolAddress(&adst, g_adst);
    cudaGetSymbolAddress(&den,  g_den);
    cudaGetSymbolAddress(&h1,   g_h1);
    cudaGetSymbolAddress(&cnt,    g_cnt);
    cudaGetSymbolAddress(&cursor, g_cursor);
    cudaGetSymbolAddress(&esort,  g_esort);

    float* den1 = (float*)den;
    float* den2 = (float*)den + (size_t)N * 8;
    int2*  es   = (int2*)esort;

    const int smem1 = (128 * 256 + 64 * 128) * 4;   // 160 KB
    const int smem2 = (32 * 128 + 128 * 32) * 4;    // 32 KB
    cudaFuncSetAttribute(gemm_att_kernel<128, 256, 32>,
                         cudaFuncAttributeMaxDynamicSharedMemorySize, smem1);

    // ---- edge sort (shared by both layers) ----
    cudaMemsetAsync(cnt, 0, NBUCK * sizeof(int), 0);
    hist_kernel<<<1024, 256>>>(ei, E, N, (int*)cnt);
    scan_kernel<<<1, 1024>>>((int*)cnt, (int*)cursor);
    scatter_kernel<<<(EN + 511) / 512, 512>>>(ei, E, N, (int*)cursor, es);

    // ---- zero accumulators ----
    cudaMemsetAsync(den,  0, (size_t)2 * N * 8 * sizeof(float), 0);
    cudaMemsetAsync(agg1, 0, (size_t)N * 32 * sizeof(float), 0);
    cudaMemsetAsync(agg2, 0, (size_t)N * 16 * sizeof(float), 0);

    // ---- layer 1 ----
    gemm_att_kernel<128, 256, 32><<<(N + 63) / 64, 512, smem1>>>(
        x, W1, as1, ad1, (float*)xh1, (float*)asrc, (float*)adst, N);
    den_kernel<<<(EN + 255) / 256, 256>>>(es, EN, (float*)asrc, (float*)adst, den1);
    aggregate1_kernel<<<((size_t)EN * 8 + 255) / 256, 256>>>(
        es, EN, (float*)xh1, (float*)asrc, (float*)adst, den1, (float*)agg1);
    finalize1_kernel<<<(N * 32 + 255) / 256, 256>>>((float*)agg1, b1, (float*)h1, N);

    // ---- layer 2 ----
    gemm_att_kernel<32, 128, 16><<<(N + 127) / 128, 512, smem2>>>(
        (float*)h1, W2, as2, ad2, (float*)xh2, (float*)asrc, (float*)adst, N);
    den_kernel<<<(EN + 255) / 256, 256>>>(es, EN, (float*)asrc, (float*)adst, den2);
    aggregate2_kernel<<<((size_t)EN * 4 + 255) / 256, 256>>>(
        es, EN, (float*)xh2, (float*)asrc, (float*)adst, den2, (float*)agg2);

    int wl = (out_size >= 2 * N * 16) ? 1 : 0;
    finalize2_kernel<<<(N * 16 + 127) / 128, 128>>>((float*)agg2, b2,
                                                    out, out + (size_t)N * 16, N, wl);
}